// round 14
// baseline (speedup 1.0000x reference)
#include <cuda_runtime.h>

#define NROWS 100000
#define DIMX  592
#define NINV  128
#define NEQ   464
#define NCH   240
#define NSEG  112
#define RTW   8        // rows per warp
#define RTC   32       // rows per CTA (4 warps)
#define NTHR  128
#define HSTR  12       // h-buffer row stride (floats); row k at 12k, extent 8
#define HWARP 1552     // per-warp h buffer floats
#define ACHUNK 8       // phase-A rows per chunk

// ---- shared memory layout (floats) ----
// Region X: x1 during GEMM1 ([k][row32]), then per-warp h buffers (warp-private)
// Region A: phase-A staging (s_ten + s_rdiv) — disjoint from X (coexist in phase A)
#define OFF_X  0
#define SZ_X   (NCH * RTC)                    // 7680 floats (30 KB) >= 4*HWARP
#define OFF_A  SZ_X
#define SZ_A   (ACHUNK * DIMX + ACHUNK * NSEG) // 4736 + 896 = 5632 floats
#define SMEM_FLOATS (OFF_A + SZ_A)            // 13312 floats = 53248 B -> 4 CTAs/SM

// ---- Blackwell packed f32x2 helpers ----
static __device__ __forceinline__ unsigned long long ffma2(unsigned long long a,
                                                           unsigned long long b,
                                                           unsigned long long c) {
    unsigned long long d;
    asm("fma.rn.f32x2 %0, %1, %2, %3;" : "=l"(d) : "l"(a), "l"(b), "l"(c));
    return d;
}
static __device__ __forceinline__ unsigned long long pack2(float x, float y) {
    unsigned long long r;
    asm("mov.b64 %0, {%1, %2};" : "=l"(r)
        : "r"(__float_as_uint(x)), "r"(__float_as_uint(y)));
    return r;
}
static __device__ __forceinline__ void unpack2(unsigned long long v, float& x, float& y) {
    unsigned a, b;
    asm("mov.b64 {%0, %1}, %2;" : "=r"(a), "=r"(b) : "l"(v));
    x = __uint_as_float(a);
    y = __uint_as_float(b);
}

// h-buffer row offset: padded stride 12 (proven). Row k: 8 contiguous floats
// at 12k, 16B aligned, max 1532 < HWARP.
static __device__ __forceinline__ int hoff(int k) {
    return k * HSTR;
}

// Register-streamed warp GEMM: 8 rows x 4 channels per thread.
// Weights flow gmem -> registers in double-buffered chunks of 4 k-rows
// (16 regs/buffer, MLP=4 outstanding LDG.128 per warp). x broadcast from shared.
// SWZ=false: x row k at xb + k*RTC (x1 layout). SWZ=true: at xb + hoff(k).
// NO CTA synchronization anywhere inside — warps run fully decoupled.
template<int K, bool SWZ>
static __device__ __forceinline__ void gemm_regs(const float* __restrict__ Wg,
                                                 const float* xb, int c0,
                                                 float4 bias, float hv[4][8]) {
    constexpr int T = K / 4;                 // 4-k chunks
    const float4* wp4 = reinterpret_cast<const float4*>(Wg + c0);   // stride NINV/4 float4s

    float4 wb[2][4];
#pragma unroll
    for (int q = 0; q < 4; q++) wb[0][q] = __ldg(wp4 + q * (NINV / 4));

    unsigned long long acc[4][4];
    {
        float bbv[4] = {bias.x, bias.y, bias.z, bias.w};
#pragma unroll
        for (int j = 0; j < 4; j++) {
            unsigned long long b = pack2(bbv[j], bbv[j]);
            acc[j][0] = b; acc[j][1] = b; acc[j][2] = b; acc[j][3] = b;
        }
    }

#pragma unroll 1
    for (int t = 0; t < T; t++) {
        const int cur = t & 1, nxt = cur ^ 1;
        // prefetch next chunk (branchless tail: reload current rows)
        const int tn = (t + 1 < T) ? t + 1 : t;
#pragma unroll
        for (int q = 0; q < 4; q++)
            wb[nxt][q] = __ldg(wp4 + (tn * 4 + q) * (NINV / 4));

#pragma unroll
        for (int kk = 0; kk < 4; kk++) {
            const int k = t * 4 + kk;
            float4 wv = wb[cur][kk];
            const float* xp = SWZ ? (xb + hoff(k)) : (xb + k * RTC);
            ulonglong2 xa = *reinterpret_cast<const ulonglong2*>(xp);
            ulonglong2 xc = *reinterpret_cast<const ulonglong2*>(xp + 4);
            unsigned long long wp0 = pack2(wv.x, wv.x);
            unsigned long long wp1 = pack2(wv.y, wv.y);
            unsigned long long wp2 = pack2(wv.z, wv.z);
            unsigned long long wp3 = pack2(wv.w, wv.w);
            acc[0][0] = ffma2(xa.x, wp0, acc[0][0]);
            acc[0][1] = ffma2(xa.y, wp0, acc[0][1]);
            acc[0][2] = ffma2(xc.x, wp0, acc[0][2]);
            acc[0][3] = ffma2(xc.y, wp0, acc[0][3]);
            acc[1][0] = ffma2(xa.x, wp1, acc[1][0]);
            acc[1][1] = ffma2(xa.y, wp1, acc[1][1]);
            acc[1][2] = ffma2(xc.x, wp1, acc[1][2]);
            acc[1][3] = ffma2(xc.y, wp1, acc[1][3]);
            acc[2][0] = ffma2(xa.x, wp2, acc[2][0]);
            acc[2][1] = ffma2(xa.y, wp2, acc[2][1]);
            acc[2][2] = ffma2(xc.x, wp2, acc[2][2]);
            acc[2][3] = ffma2(xc.y, wp2, acc[2][3]);
            acc[3][0] = ffma2(xa.x, wp3, acc[3][0]);
            acc[3][1] = ffma2(xa.y, wp3, acc[3][1]);
            acc[3][2] = ffma2(xc.x, wp3, acc[3][2]);
            acc[3][3] = ffma2(xc.y, wp3, acc[3][3]);
        }
    }
#pragma unroll
    for (int j = 0; j < 4; j++) {
        unpack2(acc[j][0], hv[j][0], hv[j][1]);
        unpack2(acc[j][1], hv[j][2], hv[j][3]);
        unpack2(acc[j][2], hv[j][4], hv[j][5]);
        unpack2(acc[j][3], hv[j][6], hv[j][7]);
    }
}

// Warp-local LayerNorm stats (128 channels across warp, 8 rows per thread set)
static __device__ __forceinline__ void ln_warp(const float hv[4][8], float* mu, float* rs) {
#pragma unroll
    for (int r = 0; r < RTW; r++) {
        float s = hv[0][r] + hv[1][r] + hv[2][r] + hv[3][r];
        float q = hv[0][r] * hv[0][r] + hv[1][r] * hv[1][r]
                + hv[2][r] * hv[2][r] + hv[3][r] * hv[3][r];
#pragma unroll
        for (int o = 16; o; o >>= 1) {
            s += __shfl_xor_sync(0xffffffffu, s, o);
            q += __shfl_xor_sync(0xffffffffu, q, o);
        }
        float m = s * (1.0f / NINV);
        mu[r] = m;
        rs[r] = rsqrtf(q * (1.0f / NINV) - m * m + 1e-5f);
    }
}

// LN affine + transposed store into per-warp (private) h buffer
static __device__ __forceinline__ void ln_store(float* shw, int c0, const float hv[4][8],
                                                const float* mu, const float* rs,
                                                float4 g4, float4 b4) {
    float gg[4] = {g4.x, g4.y, g4.z, g4.w};
    float bb[4] = {b4.x, b4.y, b4.z, b4.w};
#pragma unroll
    for (int j = 0; j < 4; j++) {
        float4 lo, hi;
        lo.x = (hv[j][0] - mu[0]) * rs[0] * gg[j] + bb[j];
        lo.y = (hv[j][1] - mu[1]) * rs[1] * gg[j] + bb[j];
        lo.z = (hv[j][2] - mu[2]) * rs[2] * gg[j] + bb[j];
        lo.w = (hv[j][3] - mu[3]) * rs[3] * gg[j] + bb[j];
        hi.x = (hv[j][4] - mu[4]) * rs[4] * gg[j] + bb[j];
        hi.y = (hv[j][5] - mu[5]) * rs[5] * gg[j] + bb[j];
        hi.z = (hv[j][6] - mu[6]) * rs[6] * gg[j] + bb[j];
        hi.w = (hv[j][7] - mu[7]) * rs[7] * gg[j] + bb[j];
        float* p = shw + hoff(c0 + j);
        *reinterpret_cast<float4*>(p)     = lo;
        *reinterpret_cast<float4*>(p + 4) = hi;
    }
}

__global__ void __launch_bounds__(NTHR, 4) evmlp_kernel(
    const float* __restrict__ ten,
    const float* __restrict__ w1, const float* __restrict__ g1, const float* __restrict__ be1,
    const float* __restrict__ w2, const float* __restrict__ b2,
    const float* __restrict__ g2, const float* __restrict__ be2,
    const float* __restrict__ w3, const float* __restrict__ b3,
    float* __restrict__ out)
{
    extern __shared__ __align__(16) float smem[];
    float* s_x1   = smem + OFF_X;
    float* s_h    = smem + OFF_X;               // alias: x1 dead after GEMM1
    float* s_ten  = smem + OFF_A;
    float* s_rdiv = smem + OFF_A + ACHUNK * DIMX;

    const int tid = threadIdx.x;

    // ---------- Phase A: 4 chunks of 8 rows -> x1 (transposed) + x2 out ----------
#pragma unroll 1
    for (int cc = 0; cc < RTC / ACHUNK; cc++) {
        const long long row0 = (long long)blockIdx.x * RTC + cc * ACHUNK;
        {
            const float4* g4 = reinterpret_cast<const float4*>(ten + row0 * DIMX);
            float4* s4 = reinterpret_cast<float4*>(s_ten);
            for (int i = tid; i < (ACHUNK * DIMX) / 4; i += NTHR) s4[i] = g4[i];
        }
        __syncthreads();

        // x10 -> s_x1 [c][row32]
        for (int j = tid; j < ACHUNK * NINV; j += NTHR) {
            int r = j & (ACHUNK - 1);
            int c = j >> 3;
            s_x1[c * RTC + cc * ACHUNK + r] = s_ten[r * DIMX + c];
        }
        // per-segment sumsq -> x11 + reciprocal divisor
        if (tid < NSEG) {
            int t = tid, base, len;
            if (t < 64)      { base = 3 * t;              len = 3; }
            else if (t < 96) { base = 192 + 5 * (t - 64); len = 5; }
            else             { base = 352 + 7 * (t - 96); len = 7; }
#pragma unroll
            for (int r = 0; r < ACHUNK; r++) {
                const float* e = &s_ten[r * DIMX + NINV + base];
                float ss = 1.0f;
                for (int j = 0; j < len; j++) ss += e[j] * e[j];
                float dv = sqrtf(ss);
                s_x1[(NINV + t) * RTC + cc * ACHUNK + r] = dv - 1.0f;
                s_rdiv[r * NSEG + t] = 1.0f / dv;
            }
        }
        __syncthreads();

        // x2 = eq * rdiv[seg] -> out columns [128, 592)
#pragma unroll 1
        for (int r = 0; r < ACHUNK; r++) {
            float*       orow = out + (row0 + r) * DIMX + NINV;
            const float* erow = &s_ten[r * DIMX + NINV];
            const float* rd   = &s_rdiv[r * NSEG];
            for (unsigned i = tid; i < NEQ; i += NTHR) {
                unsigned s;
                if (i < 192u)      s = i / 3u;
                else if (i < 352u) s = 64u + (i - 192u) / 5u;
                else               s = 96u + (i - 352u) / 7u;
                orow[i] = erow[i] * rd[s];
            }
        }
        __syncthreads();   // staging reused next chunk; also publishes x1 before GEMM1
    }

    // ---------- Phase B: per-warp MLP over its 8 rows (ZERO weight smem) ----------
    const int lane = tid & 31;
    const int wrp  = tid >> 5;
    const int c0   = lane * 4;
    const long long rowb = (long long)blockIdx.x * RTC + wrp * RTW;

    float hv[4][8], mu[RTW], rs[RTW];
    float* shw = s_h + wrp * HWARP;

    // GEMM1: h = x1 @ w1 (K = 240) — weights streamed through registers
    gemm_regs<NCH, false>(w1, s_x1 + wrp * RTW, c0,
                          make_float4(0.f, 0.f, 0.f, 0.f), hv);

    // LN1; single CTA barrier: all warps done reading x1 before h overwrites it
    ln_warp(hv, mu, rs);
    __syncthreads();
    ln_store(shw, c0, hv, mu, rs,
             __ldg(reinterpret_cast<const float4*>(g1 + c0)),
             __ldg(reinterpret_cast<const float4*>(be1 + c0)));
    __syncwarp();

    // GEMM2: h @ w2 + b2 (K = 128) — reads only this warp's private h buffer
    gemm_regs<NINV, true>(w2, shw, c0,
                          __ldg(reinterpret_cast<const float4*>(b2 + c0)), hv);

    // SiLU
#pragma unroll
    for (int j = 0; j < 4; j++)
#pragma unroll
        for (int r = 0; r < RTW; r++) {
            float v = hv[j][r];
            hv[j][r] = v / (1.0f + __expf(-v));
        }

    // LN2 (warp-private buffer: syncwarp suffices)
    ln_warp(hv, mu, rs);
    __syncwarp();   // all lanes done reading s_h from GEMM2 before overwrite
    ln_store(shw, c0, hv, mu, rs,
             __ldg(reinterpret_cast<const float4*>(g2 + c0)),
             __ldg(reinterpret_cast<const float4*>(be2 + c0)));
    __syncwarp();

    // GEMM3: h @ w3 + b3 (K = 128) -> out columns [0, 128)
    gemm_regs<NINV, true>(w3, shw, c0,
                          __ldg(reinterpret_cast<const float4*>(b3 + c0)), hv);

#pragma unroll
    for (int r = 0; r < RTW; r++) {
        float4 o;
        o.x = hv[0][r]; o.y = hv[1][r]; o.z = hv[2][r]; o.w = hv[3][r];
        *reinterpret_cast<float4*>(out + (rowb + r) * DIMX + c0) = o;
    }
}

extern "C" void kernel_launch(void* const* d_in, const int* in_sizes, int n_in,
                              void* d_out, int out_size) {
    const float* ten = (const float*)d_in[0];
    // d_in[1] = rep_layout (int64) — compile-time constant layout, unused
    const float* w1  = (const float*)d_in[2];
    const float* g1  = (const float*)d_in[3];
    const float* be1 = (const float*)d_in[4];
    const float* w2  = (const float*)d_in[5];
    const float* b2  = (const float*)d_in[6];
    const float* g2  = (const float*)d_in[7];
    const float* be2 = (const float*)d_in[8];
    const float* w3  = (const float*)d_in[9];
    const float* b3  = (const float*)d_in[10];

    static bool attr_set = false;
    if (!attr_set) {
        cudaFuncSetAttribute(evmlp_kernel,
                             cudaFuncAttributeMaxDynamicSharedMemorySize,
                             SMEM_FLOATS * (int)sizeof(float));
        attr_set = true;
    }
    evmlp_kernel<<<NROWS / RTC, NTHR, SMEM_FLOATS * sizeof(float)>>>(
        ten, w1, g1, be1, w2, b2, g2, be2, w3, b3, (float*)d_out);
}

// round 16
// speedup vs baseline: 1.8609x; 1.8609x over previous
#include <cuda_runtime.h>

#define NROWS 100000
#define DIMX  592
#define NINV  128
#define NEQ   464
#define NCH   240
#define NSEG  112
#define RTW   16       // rows per warp GEMM tile (pair-shared)
#define RTC   32       // rows per CTA (2 pairs x 16 rows)
#define NTHR  128
#define KT    8        // k-rows per weight tile
#define NBUF  3        // buffers per ring (prefetch distance 2)
#define HSTR  20       // h-buffer row stride (floats); row k at 20k, extent 16
#define HPAIR 2560     // per-pair h buffer floats (128*20)
#define ACHUNK 8       // phase-A rows per chunk

// ---- shared memory layout (floats) ----
// Region W: TWO weight rings (one per k-half) + combine scratch + phase-A staging (aliased)
// Region X: x1 during GEMM1 ([k][row32]), then per-pair h buffers
#define RINGF  (NBUF * KT * NINV)     // 3072 floats per ring
#define OFF_W  0
#define SZ_W   (2 * RINGF)            // 6144 floats (24 KB)
#define OFF_X  SZ_W
#define SZ_X   (NCH * RTC)            // 7680 floats (30 KB) >= 2*HPAIR = 5120
#define SMEM_FLOATS (OFF_X + SZ_X)    // 13824 floats = 55296 B -> 4 CTAs/SM

// ---- Blackwell packed f32x2 helpers ----
static __device__ __forceinline__ unsigned long long ffma2(unsigned long long a,
                                                           unsigned long long b,
                                                           unsigned long long c) {
    unsigned long long d;
    asm("fma.rn.f32x2 %0, %1, %2, %3;" : "=l"(d) : "l"(a), "l"(b), "l"(c));
    return d;
}
static __device__ __forceinline__ unsigned long long pack2(float x, float y) {
    unsigned long long r;
    asm("mov.b64 %0, {%1, %2};" : "=l"(r)
        : "r"(__float_as_uint(x)), "r"(__float_as_uint(y)));
    return r;
}
static __device__ __forceinline__ void unpack2(unsigned long long v, float& x, float& y) {
    unsigned a, b;
    asm("mov.b64 {%0, %1}, %2;" : "=r"(a), "=r"(b) : "l"(v));
    x = __uint_as_float(a);
    y = __uint_as_float(b);
}

static __device__ __forceinline__ int hoff(int k) { return k * HSTR; }

// 64-thread cohort async copy of one KT x 128 tile (4KB contiguous)
static __device__ __forceinline__ void copy_tile8(float* dst, const float* src, int ltid) {
#pragma unroll
    for (int i = 0; i < 4; i++) {       // 4 x 16B per thread x 64 threads
        unsigned d = (unsigned)__cvta_generic_to_shared(dst + (ltid + i * 64) * 4);
        asm volatile("cp.async.cg.shared.global [%0], [%1], 16;"
                     :: "r"(d), "l"(src + (ltid + i * 64) * 4));
    }
}
static __device__ __forceinline__ void cp_commit() {
    asm volatile("cp.async.commit_group;");
}
static __device__ __forceinline__ void cp_wait1() {
    asm volatile("cp.async.wait_group 1;");
}

// Pair-K-split staged GEMM: each warp computes 16 rows x 4 ch/lane over its
// k-half (KH values). Ring r=tid>>6 is FILLED by that thread cohort; ring
// rw=warp&1 is CONSUMED by the warp. x broadcast from shared at stride XSTR
// (xb pre-offset to this warp's rows AND k-half).
template<int KH, int XSTR>
static __device__ __forceinline__ void gemm16(const float* __restrict__ Wg,
                                              const float* xb, float* s_w,
                                              int tid, int lane, int rw,
                                              float4 bias, bool use_bias,
                                              float hv[4][RTW]) {
    constexpr int T = KH / KT;
    const int ltid = tid & 63;
    const int r    = tid >> 6;                   // ring this thread fills
    float* ringw = s_w + r * RINGF;              // fill target
    const float* Wsrc = Wg + r * KH * NINV;      // fill source (ring r's k-half)
    float* ringc = s_w + rw * RINGF;             // consume source

    __syncthreads();   // all warps done with s_w (scratch/staging) from before
#pragma unroll
    for (int p = 0; p < 2; p++) {
        copy_tile8(ringw + p * (KT * NINV), Wsrc + p * KT * NINV, ltid);
        cp_commit();
    }
    unsigned long long acc[4][8];
    {
        float bbv[4] = {bias.x, bias.y, bias.z, bias.w};
#pragma unroll
        for (int j = 0; j < 4; j++) {
            unsigned long long b = use_bias ? pack2(bbv[j], bbv[j]) : 0ull;
#pragma unroll
            for (int i = 0; i < 8; i++) acc[j][i] = b;
        }
    }
    int buf = 0, pbuf = 2;
#pragma unroll 1
    for (int t = 0; t < T; t++) {
        cp_wait1();
        __syncthreads();
        if (t + 2 < T) copy_tile8(ringw + pbuf * (KT * NINV),
                                  Wsrc + (t + 2) * KT * NINV, ltid);
        cp_commit();
        const float* wb = ringc + buf * (KT * NINV) + lane * 4;
        if (++buf == NBUF) buf = 0;
        if (++pbuf == NBUF) pbuf = 0;
#pragma unroll
        for (int kk = 0; kk < KT; kk++) {
            const int k = t * KT + kk;
            float4 wv = *reinterpret_cast<const float4*>(wb + kk * NINV);
            const float* xp = xb + k * XSTR;
            ulonglong2 q0 = *reinterpret_cast<const ulonglong2*>(xp);
            ulonglong2 q1 = *reinterpret_cast<const ulonglong2*>(xp + 4);
            ulonglong2 q2 = *reinterpret_cast<const ulonglong2*>(xp + 8);
            ulonglong2 q3 = *reinterpret_cast<const ulonglong2*>(xp + 12);
            unsigned long long xr[8] = {q0.x, q0.y, q1.x, q1.y,
                                        q2.x, q2.y, q3.x, q3.y};
            unsigned long long wp[4] = {pack2(wv.x, wv.x), pack2(wv.y, wv.y),
                                        pack2(wv.z, wv.z), pack2(wv.w, wv.w)};
#pragma unroll
            for (int j = 0; j < 4; j++)
#pragma unroll
                for (int i = 0; i < 8; i++)
                    acc[j][i] = ffma2(xr[i], wp[j], acc[j][i]);
        }
    }
#pragma unroll
    for (int j = 0; j < 4; j++)
#pragma unroll
        for (int i = 0; i < 8; i++)
            unpack2(acc[j][i], hv[j][2 * i], hv[j][2 * i + 1]);
}

// Symmetric pair combine: even warp (rw=0) stores rows 8-15, keeps 0-7;
// odd warp stores rows 0-7, keeps 8-15. After the barrier each adds the
// counterpart's stored half and owns 8 fully-summed rows (offset rw*8).
static __device__ __forceinline__ void combine_pair(float hv[4][RTW], float* scrp,
                                                    int rw, int lane) {
    float* myblk = scrp + rw * 1024;
    float* otblk = scrp + (1 - rw) * 1024;
    const int sro = (1 - rw) * 8;    // rows this warp stores
    const int kro = rw * 8;          // rows this warp keeps
#pragma unroll
    for (int j = 0; j < 4; j++)
#pragma unroll
        for (int rg = 0; rg < 2; rg++) {
            float4 v = make_float4(hv[j][sro + 4 * rg + 0], hv[j][sro + 4 * rg + 1],
                                   hv[j][sro + 4 * rg + 2], hv[j][sro + 4 * rg + 3]);
            *reinterpret_cast<float4*>(myblk + (j * 2 + rg) * 128 + lane * 4) = v;
        }
    __syncthreads();
#pragma unroll
    for (int j = 0; j < 4; j++)
#pragma unroll
        for (int rg = 0; rg < 2; rg++) {
            float4 v = *reinterpret_cast<const float4*>(otblk + (j * 2 + rg) * 128 + lane * 4);
            hv[j][kro + 4 * rg + 0] += v.x;
            hv[j][kro + 4 * rg + 1] += v.y;
            hv[j][kro + 4 * rg + 2] += v.z;
            hv[j][kro + 4 * rg + 3] += v.w;
        }
}

// Warp-local LayerNorm over 8 rows at offset ro in hv
static __device__ __forceinline__ void ln8(const float hv[4][RTW], int ro,
                                           float* mu, float* rs) {
#pragma unroll
    for (int r = 0; r < 8; r++) {
        float a = hv[0][ro + r], b = hv[1][ro + r], c = hv[2][ro + r], d = hv[3][ro + r];
        float s = a + b + c + d;
        float q = a * a + b * b + c * c + d * d;
#pragma unroll
        for (int o = 16; o; o >>= 1) {
            s += __shfl_xor_sync(0xffffffffu, s, o);
            q += __shfl_xor_sync(0xffffffffu, q, o);
        }
        float m = s * (1.0f / NINV);
        mu[r] = m;
        rs[r] = rsqrtf(q * (1.0f / NINV) - m * m + 1e-5f);
    }
}

// LN affine + transposed store of this warp's 8 rows into the pair h buffer
static __device__ __forceinline__ void ln_store8(float* hp, int c0, const float hv[4][RTW],
                                                 int ro, const float* mu, const float* rs,
                                                 float4 g4, float4 b4) {
    float gg[4] = {g4.x, g4.y, g4.z, g4.w};
    float bb[4] = {b4.x, b4.y, b4.z, b4.w};
#pragma unroll
    for (int j = 0; j < 4; j++) {
        float4 lo, hi;
        lo.x = (hv[j][ro + 0] - mu[0]) * rs[0] * gg[j] + bb[j];
        lo.y = (hv[j][ro + 1] - mu[1]) * rs[1] * gg[j] + bb[j];
        lo.z = (hv[j][ro + 2] - mu[2]) * rs[2] * gg[j] + bb[j];
        lo.w = (hv[j][ro + 3] - mu[3]) * rs[3] * gg[j] + bb[j];
        hi.x = (hv[j][ro + 4] - mu[4]) * rs[4] * gg[j] + bb[j];
        hi.y = (hv[j][ro + 5] - mu[5]) * rs[5] * gg[j] + bb[j];
        hi.z = (hv[j][ro + 6] - mu[6]) * rs[6] * gg[j] + bb[j];
        hi.w = (hv[j][ro + 7] - mu[7]) * rs[7] * gg[j] + bb[j];
        float* p = hp + hoff(c0 + j) + ro;
        *reinterpret_cast<float4*>(p)     = lo;
        *reinterpret_cast<float4*>(p + 4) = hi;
    }
}

__global__ void __launch_bounds__(NTHR, 4) evmlp_kernel(
    const float* __restrict__ ten,
    const float* __restrict__ w1, const float* __restrict__ g1, const float* __restrict__ be1,
    const float* __restrict__ w2, const float* __restrict__ b2,
    const float* __restrict__ g2, const float* __restrict__ be2,
    const float* __restrict__ w3, const float* __restrict__ b3,
    float* __restrict__ out)
{
    extern __shared__ __align__(16) float smem[];
    float* s_w    = smem + OFF_W;
    float* s_x1   = smem + OFF_X;
    float* s_h    = smem + OFF_X;               // alias: x1 dead after GEMM1
    float* s_ten  = s_w;                        // phase-A alias (4736 <= 6144)
    float* s_rdiv = s_w + ACHUNK * DIMX;        // phase-A alias (+896 <= 6144)

    const int tid = threadIdx.x;

    // ---------- Phase A: 4 chunks of 8 rows -> x1 (transposed) + x2 out ----------
#pragma unroll 1
    for (int cc = 0; cc < RTC / ACHUNK; cc++) {
        const long long row0 = (long long)blockIdx.x * RTC + cc * ACHUNK;
        {
            const float4* g4 = reinterpret_cast<const float4*>(ten + row0 * DIMX);
            float4* s4 = reinterpret_cast<float4*>(s_ten);
            for (int i = tid; i < (ACHUNK * DIMX) / 4; i += NTHR) s4[i] = g4[i];
        }
        __syncthreads();

        // x10 -> s_x1 [c][row32]
        for (int j = tid; j < ACHUNK * NINV; j += NTHR) {
            int r = j & (ACHUNK - 1);
            int c = j >> 3;
            s_x1[c * RTC + cc * ACHUNK + r] = s_ten[r * DIMX + c];
        }
        // per-segment sumsq -> x11 + reciprocal divisor
        if (tid < NSEG) {
            int t = tid, base, len;
            if (t < 64)      { base = 3 * t;              len = 3; }
            else if (t < 96) { base = 192 + 5 * (t - 64); len = 5; }
            else             { base = 352 + 7 * (t - 96); len = 7; }
#pragma unroll
            for (int r = 0; r < ACHUNK; r++) {
                const float* e = &s_ten[r * DIMX + NINV + base];
                float ss = 1.0f;
                for (int j = 0; j < len; j++) ss += e[j] * e[j];
                float dv = sqrtf(ss);
                s_x1[(NINV + t) * RTC + cc * ACHUNK + r] = dv - 1.0f;
                s_rdiv[r * NSEG + t] = 1.0f / dv;
            }
        }
        __syncthreads();

        // x2 = eq * rdiv[seg] -> out columns [128, 592)
#pragma unroll 1
        for (int r = 0; r < ACHUNK; r++) {
            float*       orow = out + (row0 + r) * DIMX + NINV;
            const float* erow = &s_ten[r * DIMX + NINV];
            const float* rd   = &s_rdiv[r * NSEG];
            for (unsigned i = tid; i < NEQ; i += NTHR) {
                unsigned s;
                if (i < 192u)      s = i / 3u;
                else if (i < 352u) s = 64u + (i - 192u) / 5u;
                else               s = 96u + (i - 352u) / 7u;
                orow[i] = erow[i] * rd[s];
            }
        }
        __syncthreads();
    }

    // ---------- Phase B: pair K-split MLP ----------
    const int lane = tid & 31;
    const int wrp  = tid >> 5;
    const int rw   = wrp & 1;        // k-half of this warp
    const int pair = wrp >> 1;       // row group (16 rows)
    const int c0   = lane * 4;
    const int ro   = rw * 8;         // rows owned after combine

    float hv[4][RTW], mu[8], rs[8];
    float* scrp = s_w + pair * 2048;           // combine scratch (ring area, idle)
    float* hp   = s_h + pair * HPAIR;          // pair h buffer

    // GEMM1: K=240 split 120/120
    gemm16<120, RTC>(w1, s_x1 + pair * RTW + rw * 120 * RTC, s_w, tid, lane, rw,
                     make_float4(0.f, 0.f, 0.f, 0.f), false, hv);
    combine_pair(hv, scrp, rw, lane);          // also: all warps past x1 reads

    // LN1 on owned 8 rows -> h buffer
    ln8(hv, ro, mu, rs);
    ln_store8(hp, c0, hv, ro, mu, rs,
              __ldg(reinterpret_cast<const float4*>(g1 + c0)),
              __ldg(reinterpret_cast<const float4*>(be1 + c0)));

    // GEMM2: K=128 split 64/64 (entry barrier publishes h)
    gemm16<64, HSTR>(w2, hp + rw * 64 * HSTR, s_w, tid, lane, rw,
                     __ldg(reinterpret_cast<const float4*>(b2 + c0)), rw == 0, hv);
    combine_pair(hv, scrp, rw, lane);

    // SiLU + LN2 on owned rows
#pragma unroll
    for (int j = 0; j < 4; j++)
#pragma unroll
        for (int r = 0; r < 8; r++) {
            float v = hv[j][ro + r];
            hv[j][ro + r] = v / (1.0f + __expf(-v));
        }
    ln8(hv, ro, mu, rs);
    ln_store8(hp, c0, hv, ro, mu, rs,
              __ldg(reinterpret_cast<const float4*>(g2 + c0)),
              __ldg(reinterpret_cast<const float4*>(be2 + c0)));

    // GEMM3: K=128 split 64/64
    gemm16<64, HSTR>(w3, hp + rw * 64 * HSTR, s_w, tid, lane, rw,
                     __ldg(reinterpret_cast<const float4*>(b3 + c0)), rw == 0, hv);
    combine_pair(hv, scrp, rw, lane);

    // write owned 8 rows -> out columns [0,128)
    const long long rowb = (long long)blockIdx.x * RTC + pair * RTW + ro;
#pragma unroll
    for (int r = 0; r < 8; r++) {
        float4 o;
        o.x = hv[0][ro + r]; o.y = hv[1][ro + r];
        o.z = hv[2][ro + r]; o.w = hv[3][ro + r];
        *reinterpret_cast<float4*>(out + (rowb + r) * DIMX + c0) = o;
    }
}

extern "C" void kernel_launch(void* const* d_in, const int* in_sizes, int n_in,
                              void* d_out, int out_size) {
    const float* ten = (const float*)d_in[0];
    // d_in[1] = rep_layout (int64) — compile-time constant layout, unused
    const float* w1  = (const float*)d_in[2];
    const float* g1  = (const float*)d_in[3];
    const float* be1 = (const float*)d_in[4];
    const float* w2  = (const float*)d_in[5];
    const float* b2  = (const float*)d_in[6];
    const float* g2  = (const float*)d_in[7];
    const float* be2 = (const float*)d_in[8];
    const float* w3  = (const float*)d_in[9];
    const float* b3  = (const float*)d_in[10];

    static bool attr_set = false;
    if (!attr_set) {
        cudaFuncSetAttribute(evmlp_kernel,
                             cudaFuncAttributeMaxDynamicSharedMemorySize,
                             SMEM_FLOATS * (int)sizeof(float));
        attr_set = true;
    }
    evmlp_kernel<<<NROWS / RTC, NTHR, SMEM_FLOATS * sizeof(float)>>>(
        ten, w1, g1, be1, w2, b2, g2, be2, w3, b3, (float*)d_out);
}

// round 17
// speedup vs baseline: 1.8731x; 1.0065x over previous
#include <cuda_runtime.h>

#define NROWS 100000
#define DIMX  592
#define NINV  128
#define NEQ   464
#define NCH   240
#define NSEG  112
#define RTW   16       // rows per warp
#define RTC   64       // rows per CTA (4 warps x 16)
#define NTHR  128
#define KT    16       // k-rows per weight tile
#define NBUF  3        // async weight buffers (prefetch distance 2)
#define HSTR  16       // h-buffer row stride (floats): row k at 16k, 16 contiguous
#define HWARP 2048     // per-warp h floats (128*16); 4 warps = 8192 = region X
#define ACHUNK 8       // phase-A rows per chunk

// ---- shared memory layout (floats) ----
// Region W: weight ring (phase A/A2: aliased as staging)
// Region X: x11 (pass A) -> x10 (pass B) -> h buffers. 8192 floats.
#define RINGF  (NBUF * KT * NINV)     // 6144 floats (24 KB)
#define OFF_W  0
#define OFF_X  RINGF
#define SZ_X   8192                   // 32 KB
#define SMEM_FLOATS (OFF_X + SZ_X)    // 14336 floats = 57344 B = 56 KB -> 4 CTAs/SM

// ---- Blackwell packed f32x2 helpers ----
static __device__ __forceinline__ unsigned long long ffma2(unsigned long long a,
                                                           unsigned long long b,
                                                           unsigned long long c) {
    unsigned long long d;
    asm("fma.rn.f32x2 %0, %1, %2, %3;" : "=l"(d) : "l"(a), "l"(b), "l"(c));
    return d;
}
static __device__ __forceinline__ unsigned long long pack2(float x, float y) {
    unsigned long long r;
    asm("mov.b64 %0, {%1, %2};" : "=l"(r)
        : "r"(__float_as_uint(x)), "r"(__float_as_uint(y)));
    return r;
}
static __device__ __forceinline__ void unpack2(unsigned long long v, float& x, float& y) {
    unsigned a, b;
    asm("mov.b64 {%0, %1}, %2;" : "=r"(a), "=r"(b) : "l"(v));
    x = __uint_as_float(a);
    y = __uint_as_float(b);
}

// cooperative async copy of one KT x 128 weight tile (8KB contiguous)
static __device__ __forceinline__ void copy_tile(float* dst, const float* src, int tid) {
#pragma unroll
    for (int i = 0; i < (KT * NINV) / (4 * NTHR); i++) {   // 4 x 16B per thread
        unsigned d = (unsigned)__cvta_generic_to_shared(dst + (tid + i * NTHR) * 4);
        asm volatile("cp.async.cg.shared.global [%0], [%1], 16;"
                     :: "r"(d), "l"(src + (tid + i * NTHR) * 4));
    }
}
static __device__ __forceinline__ void cp_commit() {
    asm volatile("cp.async.commit_group;");
}
static __device__ __forceinline__ void cp_wait1() {
    asm volatile("cp.async.wait_group 1;");
}

// Staged-weight GEMM core: accumulates T*KT k-steps into acc (16 rows x 4 ch
// per thread). Weights streamed via the shared ring; x broadcast from shared
// at row stride XSTR (xb pre-offset to this warp's rows).
template<int T, int XSTR>
static __device__ __forceinline__ void gemm_core(const float* __restrict__ Wg,
                                                 const float* xb, float* s_w,
                                                 int tid, int lane,
                                                 unsigned long long acc[4][8]) {
    __syncthreads();   // ring free + x published, all warps past prior reads
#pragma unroll
    for (int p = 0; p < 2; p++) {
        copy_tile(s_w + p * (KT * NINV), Wg + p * KT * NINV, tid);
        cp_commit();
    }
    int buf = 0, pbuf = 2;
#pragma unroll 1
    for (int t = 0; t < T; t++) {
        cp_wait1();            // tile t landed
        __syncthreads();       // visible CTA-wide; buffer pbuf fully consumed
        if (t + 2 < T) copy_tile(s_w + pbuf * (KT * NINV),
                                 Wg + (t + 2) * KT * NINV, tid);
        cp_commit();
        const float* wb = s_w + buf * (KT * NINV) + lane * 4;
        if (++buf == NBUF) buf = 0;
        if (++pbuf == NBUF) pbuf = 0;
#pragma unroll
        for (int kk = 0; kk < KT; kk++) {
            const int k = t * KT + kk;
            float4 wv = *reinterpret_cast<const float4*>(wb + kk * NINV);
            const float* xp = xb + k * XSTR;
            ulonglong2 q0 = *reinterpret_cast<const ulonglong2*>(xp);
            ulonglong2 q1 = *reinterpret_cast<const ulonglong2*>(xp + 4);
            ulonglong2 q2 = *reinterpret_cast<const ulonglong2*>(xp + 8);
            ulonglong2 q3 = *reinterpret_cast<const ulonglong2*>(xp + 12);
            unsigned long long xr[8] = {q0.x, q0.y, q1.x, q1.y,
                                        q2.x, q2.y, q3.x, q3.y};
            unsigned long long wp[4] = {pack2(wv.x, wv.x), pack2(wv.y, wv.y),
                                        pack2(wv.z, wv.z), pack2(wv.w, wv.w)};
#pragma unroll
            for (int j = 0; j < 4; j++)
#pragma unroll
                for (int i = 0; i < 8; i++)
                    acc[j][i] = ffma2(xr[i], wp[j], acc[j][i]);
        }
    }
}

static __device__ __forceinline__ void acc_init(unsigned long long acc[4][8],
                                                float4 bias) {
    float bbv[4] = {bias.x, bias.y, bias.z, bias.w};
#pragma unroll
    for (int j = 0; j < 4; j++) {
        unsigned long long b = pack2(bbv[j], bbv[j]);
#pragma unroll
        for (int i = 0; i < 8; i++) acc[j][i] = b;
    }
}
static __device__ __forceinline__ void acc_out(const unsigned long long acc[4][8],
                                               float hv[4][RTW]) {
#pragma unroll
    for (int j = 0; j < 4; j++)
#pragma unroll
        for (int i = 0; i < 8; i++)
            unpack2(acc[j][i], hv[j][2 * i], hv[j][2 * i + 1]);
}

// Warp-local LayerNorm stats over this warp's 16 rows
static __device__ __forceinline__ void ln_warp(const float hv[4][RTW], float* mu, float* rs) {
#pragma unroll
    for (int r = 0; r < RTW; r++) {
        float s = hv[0][r] + hv[1][r] + hv[2][r] + hv[3][r];
        float q = hv[0][r] * hv[0][r] + hv[1][r] * hv[1][r]
                + hv[2][r] * hv[2][r] + hv[3][r] * hv[3][r];
#pragma unroll
        for (int o = 16; o; o >>= 1) {
            s += __shfl_xor_sync(0xffffffffu, s, o);
            q += __shfl_xor_sync(0xffffffffu, q, o);
        }
        float m = s * (1.0f / NINV);
        mu[r] = m;
        rs[r] = rsqrtf(q * (1.0f / NINV) - m * m + 1e-5f);
    }
}

// LN affine + transposed store into per-warp h buffer (stride 16)
static __device__ __forceinline__ void ln_store(float* hp, int c0, const float hv[4][RTW],
                                                const float* mu, const float* rs,
                                                float4 g4, float4 b4) {
    float gg[4] = {g4.x, g4.y, g4.z, g4.w};
    float bb[4] = {b4.x, b4.y, b4.z, b4.w};
#pragma unroll
    for (int j = 0; j < 4; j++) {
        float* p = hp + (c0 + j) * HSTR;
#pragma unroll
        for (int q = 0; q < 4; q++) {
            float4 v;
            v.x = (hv[j][4 * q + 0] - mu[4 * q + 0]) * rs[4 * q + 0] * gg[j] + bb[j];
            v.y = (hv[j][4 * q + 1] - mu[4 * q + 1]) * rs[4 * q + 1] * gg[j] + bb[j];
            v.z = (hv[j][4 * q + 2] - mu[4 * q + 2]) * rs[4 * q + 2] * gg[j] + bb[j];
            v.w = (hv[j][4 * q + 3] - mu[4 * q + 3]) * rs[4 * q + 3] * gg[j] + bb[j];
            *reinterpret_cast<float4*>(p + 4 * q) = v;
        }
    }
}

__global__ void __launch_bounds__(NTHR, 4) evmlp_kernel(
    const float* __restrict__ ten,
    const float* __restrict__ w1, const float* __restrict__ g1, const float* __restrict__ be1,
    const float* __restrict__ w2, const float* __restrict__ b2,
    const float* __restrict__ g2, const float* __restrict__ be2,
    const float* __restrict__ w3, const float* __restrict__ b3,
    float* __restrict__ out)
{
    extern __shared__ __align__(16) float smem[];
    float* s_w    = smem + OFF_W;               // ring / phase-A staging
    float* s_x    = smem + OFF_X;               // x11 -> x10 -> h
    float* s_ten  = s_w;                        // phase-A alias (4736 <= 6144)
    float* s_rdiv = s_w + ACHUNK * DIMX;        // phase-A alias (+896 <= 6144)

    const int tid = threadIdx.x;

    // ---------- Phase A: 8 chunks of 8 rows -> x11 ([112][64]) + x2 out ----------
#pragma unroll 1
    for (int cc = 0; cc < RTC / ACHUNK; cc++) {
        const long long row0 = (long long)blockIdx.x * RTC + cc * ACHUNK;
        if (row0 >= NROWS) break;               // uniform per CTA
        {
            const float4* g4 = reinterpret_cast<const float4*>(ten + row0 * DIMX);
            float4* s4 = reinterpret_cast<float4*>(s_ten);
            for (int i = tid; i < (ACHUNK * DIMX) / 4; i += NTHR) s4[i] = g4[i];
        }
        __syncthreads();

        // per-segment sumsq -> x11 (stride 64) + reciprocal divisor
        if (tid < NSEG) {
            int t = tid, base, len;
            if (t < 64)      { base = 3 * t;              len = 3; }
            else if (t < 96) { base = 192 + 5 * (t - 64); len = 5; }
            else             { base = 352 + 7 * (t - 96); len = 7; }
#pragma unroll
            for (int r = 0; r < ACHUNK; r++) {
                const float* e = &s_ten[r * DIMX + NINV + base];
                float ss = 1.0f;
                for (int j = 0; j < len; j++) ss += e[j] * e[j];
                float dv = sqrtf(ss);
                s_x[t * RTC + cc * ACHUNK + r] = dv - 1.0f;
                s_rdiv[r * NSEG + t] = 1.0f / dv;
            }
        }
        __syncthreads();

        // x2 = eq * rdiv[seg] -> out columns [128, 592)
#pragma unroll 1
        for (int r = 0; r < ACHUNK; r++) {
            float*       orow = out + (row0 + r) * DIMX + NINV;
            const float* erow = &s_ten[r * DIMX + NINV];
            const float* rd   = &s_rdiv[r * NSEG];
            for (unsigned i = tid; i < NEQ; i += NTHR) {
                unsigned s;
                if (i < 192u)      s = i / 3u;
                else if (i < 352u) s = 64u + (i - 192u) / 5u;
                else               s = 96u + (i - 352u) / 7u;
                orow[i] = erow[i] * rd[s];
            }
        }
        __syncthreads();
    }

    // ---------- Phase B ----------
    const int lane = tid & 31;
    const int wrp  = tid >> 5;
    const int c0   = lane * 4;
    const long long rowb = (long long)blockIdx.x * RTC + wrp * RTW;

    unsigned long long acc[4][8];
    float hv[4][RTW], mu[RTW], rs[RTW];
    float* hp = s_x + wrp * HWARP;

    // GEMM1 pass A: K=112 (x11 channels, weight rows 128..239)
    acc_init(acc, make_float4(0.f, 0.f, 0.f, 0.f));
    gemm_core<NSEG / KT, RTC>(w1 + NINV * NINV, s_x + wrp * RTW, s_w,
                              tid, lane, acc);

    // A2: transpose ten cols [0,128) of this CTA's 64 rows into s_x ([128][64])
    asm volatile("cp.async.wait_all;" ::: "memory");
#pragma unroll 1
    for (int cc = 0; cc < RTC / ACHUNK; cc++) {
        const long long row0 = (long long)blockIdx.x * RTC + cc * ACHUNK;
        if (row0 >= NROWS) break;
        __syncthreads();     // pass-A x11 reads done (cc=0) / prev transpose reads done
        {
            float4* s4 = reinterpret_cast<float4*>(s_w);
            for (int i = tid; i < ACHUNK * (NINV / 4); i += NTHR) {
                int r = i >> 5, q = i & 31;
                s4[i] = reinterpret_cast<const float4*>(ten + (row0 + r) * DIMX)[q];
            }
        }
        __syncthreads();
        for (int j = tid; j < ACHUNK * NINV; j += NTHR) {
            int r = j & (ACHUNK - 1);
            int c = j >> 3;
            s_x[c * RTC + cc * ACHUNK + r] = s_w[r * NINV + c];
        }
    }

    // GEMM1 pass B: K=128 (x10 channels, weight rows 0..127); entry barrier
    // publishes the transpose.
    gemm_core<NINV / KT, RTC>(w1, s_x + wrp * RTW, s_w, tid, lane, acc);
    acc_out(acc, hv);

    // LN1; barrier: all warps done reading x10 before h overwrites region X
    ln_warp(hv, mu, rs);
    __syncthreads();
    ln_store(hp, c0, hv, mu, rs,
             __ldg(reinterpret_cast<const float4*>(g1 + c0)),
             __ldg(reinterpret_cast<const float4*>(be1 + c0)));
    __syncwarp();

    // GEMM2: h @ w2 + b2 (K = 128), h warp-private
    acc_init(acc, __ldg(reinterpret_cast<const float4*>(b2 + c0)));
    gemm_core<NINV / KT, HSTR>(w2, hp, s_w, tid, lane, acc);
    acc_out(acc, hv);

    // SiLU
#pragma unroll
    for (int j = 0; j < 4; j++)
#pragma unroll
        for (int r = 0; r < RTW; r++) {
            float v = hv[j][r];
            hv[j][r] = v / (1.0f + __expf(-v));
        }

    // LN2 (warp-private h: syncwarp suffices)
    ln_warp(hv, mu, rs);
    __syncwarp();
    ln_store(hp, c0, hv, mu, rs,
             __ldg(reinterpret_cast<const float4*>(g2 + c0)),
             __ldg(reinterpret_cast<const float4*>(be2 + c0)));
    __syncwarp();

    // GEMM3: h @ w3 + b3 (K = 128) -> out columns [0, 128)
    acc_init(acc, __ldg(reinterpret_cast<const float4*>(b3 + c0)));
    gemm_core<NINV / KT, HSTR>(w3, hp, s_w, tid, lane, acc);
    acc_out(acc, hv);

#pragma unroll
    for (int r = 0; r < RTW; r++) {
        if (rowb + r < NROWS) {
            float4 o;
            o.x = hv[0][r]; o.y = hv[1][r]; o.z = hv[2][r]; o.w = hv[3][r];
            *reinterpret_cast<float4*>(out + (rowb + r) * DIMX + c0) = o;
        }
    }
}

extern "C" void kernel_launch(void* const* d_in, const int* in_sizes, int n_in,
                              void* d_out, int out_size) {
    const float* ten = (const float*)d_in[0];
    // d_in[1] = rep_layout (int64) — compile-time constant layout, unused
    const float* w1  = (const float*)d_in[2];
    const float* g1  = (const float*)d_in[3];
    const float* be1 = (const float*)d_in[4];
    const float* w2  = (const float*)d_in[5];
    const float* b2  = (const float*)d_in[6];
    const float* g2  = (const float*)d_in[7];
    const float* be2 = (const float*)d_in[8];
    const float* w3  = (const float*)d_in[9];
    const float* b3  = (const float*)d_in[10];

    static bool attr_set = false;
    if (!attr_set) {
        cudaFuncSetAttribute(evmlp_kernel,
                             cudaFuncAttributeMaxDynamicSharedMemorySize,
                             SMEM_FLOATS * (int)sizeof(float));
        attr_set = true;
    }
    const int grid = (NROWS + RTC - 1) / RTC;   // 1563, last CTA tail-guarded
    evmlp_kernel<<<grid, NTHR, SMEM_FLOATS * sizeof(float)>>>(
        ten, w1, g1, be1, w2, b2, g2, be2, w3, b3, (float*)d_out);
}